// round 1
// baseline (speedup 1.0000x reference)
#include <cuda_runtime.h>

#define F 128
#define NMAX 100000
#define EMAX 1600000

// ---- device scratch (no allocations allowed) ----
__device__ float g_h[(size_t)NMAX * F];      // x @ W
__device__ float g_deg[NMAX];
__device__ float g_dinv[NMAX];
__device__ int   g_counts[NMAX];
__device__ int   g_rowstart[NMAX + 1];
__device__ int   g_cursor[NMAX];
__device__ int   g_csr_src[EMAX];
__device__ float g_csr_norm[EMAX];

// ---- kernels ----

__global__ void init_kernel(int n) {
    int i = blockIdx.x * blockDim.x + threadIdx.x;
    if (i < n) {
        g_deg[i]    = 1.0f;   // self-loop weight
        g_counts[i] = 0;
        g_cursor[i] = 0;
    }
}

// deg[dst] += w ; counts[dst] += 1  (edge_index is [2, E] row-major: src then dst)
__global__ void deg_kernel(const int* __restrict__ ei, const float* __restrict__ ew, int e) {
    int i = blockIdx.x * blockDim.x + threadIdx.x;
    if (i < e) {
        int d = ei[e + i];
        atomicAdd(&g_deg[d], ew[i]);
        atomicAdd(&g_counts[d], 1);
    }
}

__global__ void dinv_kernel(int n) {
    int i = blockIdx.x * blockDim.x + threadIdx.x;
    if (i < n) {
        float dg = g_deg[i];
        g_dinv[i] = (dg > 0.0f) ? rsqrtf(dg) : 0.0f;
    }
}

// single-block exclusive scan of g_counts -> g_rowstart (n up to 100k)
__global__ void scan_kernel(int n) {
    __shared__ int partial[1025];
    int tid   = threadIdx.x;
    int nthr  = blockDim.x;
    int chunk = (n + nthr - 1) / nthr;
    int begin = tid * chunk;
    int end   = begin + chunk; if (end > n) end = n;
    int s = 0;
    for (int i = begin; i < end; i++) s += g_counts[i];
    partial[tid] = s;
    __syncthreads();
    if (tid == 0) {
        int run = 0;
        for (int i = 0; i < nthr; i++) { int t = partial[i]; partial[i] = run; run += t; }
        partial[nthr] = run;
    }
    __syncthreads();
    int run = partial[tid];
    for (int i = begin; i < end; i++) { g_rowstart[i] = run; run += g_counts[i]; }
    if (tid == 0) g_rowstart[n] = partial[nthr];
}

// fill CSR: slot = rowstart[dst] + cursor[dst]++; store src and precomputed norm
__global__ void fill_kernel(const int* __restrict__ ei, const float* __restrict__ ew, int e) {
    int i = blockIdx.x * blockDim.x + threadIdx.x;
    if (i < e) {
        int s = ei[i];
        int d = ei[e + i];
        float nm = g_dinv[s] * ew[i] * g_dinv[d];
        int pos  = atomicAdd(&g_cursor[d], 1);
        int slot = g_rowstart[d] + pos;
        g_csr_src[slot]  = s;
        g_csr_norm[slot] = nm;
    }
}

// h = x @ W  (W[k*F+f] row-major). 128 threads (one per out column), 4 rows/block.
__global__ void gemm_kernel(const float* __restrict__ x, const float* __restrict__ W, int n) {
    __shared__ float xs[4][F];
    int f    = threadIdx.x;
    int row0 = blockIdx.x * 4;
    if (row0 >= n) return;
#pragma unroll
    for (int r = 0; r < 4; r++) {
        int row = row0 + r;
        xs[r][f] = (row < n) ? x[(size_t)row * F + f] : 0.0f;
    }
    __syncthreads();
    float a0 = 0.f, a1 = 0.f, a2 = 0.f, a3 = 0.f;
#pragma unroll 8
    for (int k = 0; k < F; k++) {
        float wv = W[k * F + f];
        a0 += xs[0][k] * wv;
        a1 += xs[1][k] * wv;
        a2 += xs[2][k] * wv;
        a3 += xs[3][k] * wv;
    }
    if (row0     < n) g_h[(size_t)(row0    ) * F + f] = a0;
    if (row0 + 1 < n) g_h[(size_t)(row0 + 1) * F + f] = a1;
    if (row0 + 2 < n) g_h[(size_t)(row0 + 2) * F + f] = a2;
    if (row0 + 3 < n) g_h[(size_t)(row0 + 3) * F + f] = a3;
}

// Warp per destination node: gather in-edges from CSR (no atomics),
// add self-loop + bias, write emb and relu(emb).
__global__ void gather_kernel(const float* __restrict__ bias, float* __restrict__ out, int n) {
    int gtid = blockIdx.x * blockDim.x + threadIdx.x;
    int node = gtid >> 5;
    int lane = threadIdx.x & 31;
    if (node >= n) return;

    float4 acc = make_float4(0.f, 0.f, 0.f, 0.f);
    int beg = g_rowstart[node];
    int end = g_rowstart[node + 1];
    for (int j = beg; j < end; j++) {
        int   s  = g_csr_src[j];
        float nm = g_csr_norm[j];
        const float4* hr = (const float4*)(g_h + (size_t)s * F);
        float4 hv = hr[lane];
        acc.x += hv.x * nm; acc.y += hv.y * nm;
        acc.z += hv.z * nm; acc.w += hv.w * nm;
    }
    // self loop: norm = dinv[node] * 1 * dinv[node]
    float di = g_dinv[node];
    float sn = di * di;
    {
        const float4* hr = (const float4*)(g_h + (size_t)node * F);
        float4 hv = hr[lane];
        acc.x += hv.x * sn; acc.y += hv.y * sn;
        acc.z += hv.z * sn; acc.w += hv.w * sn;
    }
    float4 bv = ((const float4*)bias)[lane];
    acc.x += bv.x; acc.y += bv.y; acc.z += bv.z; acc.w += bv.w;

    size_t off = (size_t)node * F + (size_t)lane * 4;
    *(float4*)(out + off) = acc;

    float4 r;
    r.x = acc.x > 0.f ? acc.x : 0.f;
    r.y = acc.y > 0.f ? acc.y : 0.f;
    r.z = acc.z > 0.f ? acc.z : 0.f;
    r.w = acc.w > 0.f ? acc.w : 0.f;
    *(float4*)(out + (size_t)n * F + off) = r;
}

// ---- launch ----
// inputs (metadata order): x[N,128] f32, W[128,128] f32, b[128] f32,
//                          level i32 (unused), edge_index[2,E] i32, edge_weight[E] f32
// output: [2, N, 128] f32 -> emb then relu(emb)
extern "C" void kernel_launch(void* const* d_in, const int* in_sizes, int n_in,
                              void* d_out, int out_size) {
    const float* x  = (const float*)d_in[0];
    const float* W  = (const float*)d_in[1];
    const float* b  = (const float*)d_in[2];
    const int*   ei = (const int*)d_in[4];
    const float* ew = (const float*)d_in[5];
    float* out = (float*)d_out;

    int n = in_sizes[0] / F;
    int e = in_sizes[5];

    int nb_n = (n + 255) / 256;
    int nb_e = (e + 255) / 256;

    // GEMM is independent of the graph-structure chain; launch first.
    gemm_kernel<<<(n + 3) / 4, 128>>>(x, W, n);

    init_kernel<<<nb_n, 256>>>(n);
    deg_kernel<<<nb_e, 256>>>(ei, ew, e);
    dinv_kernel<<<nb_n, 256>>>(n);
    scan_kernel<<<1, 1024>>>(n);
    fill_kernel<<<nb_e, 256>>>(ei, ew, e);

    gather_kernel<<<(n * 32 + 255) / 256, 256>>>(b, out, n);
}